// round 5
// baseline (speedup 1.0000x reference)
#include <cuda_runtime.h>
#include <cstdint>

constexpr int NT = 224;

// ---------------- shared-memory layout (floats) ----------------
constexpr int O_W000 = 0;      // 4096 (16,16,16)
constexpr int O_W110 = 4096;   // 1024 (8,8,16)
constexpr int O_W220 = 5120;   // 1024
constexpr int O_W011 = 6144;   // 1024 (16,8,8)
constexpr int O_W101 = 7168;   // 1024 (8,16,8)
constexpr int O_W121 = 8192;   // 512  (8,8,8)
constexpr int O_W211 = 8704;   // 512
constexpr int O_W022 = 9216;   // 1024 (16,8,8)
constexpr int O_W202 = 10240;  // 1024 (8,16,8)
constexpr int O_W112 = 11264;  // 512
constexpr int O_W222 = 11776;  // 512
// per-thread staging: [feat][tid], lane-indexed, conflict-free
constexpr int O_H1   = 12288;             // 24*NT
constexpr int O_A1   = O_H1 + 24*NT;      // 24*NT
constexpr int O_A2   = O_A1 + 24*NT;      // 24*NT
constexpr int SMEM_FLOATS = O_A2 + 24*NT; // 12288 + 16128 = 28416 floats = 113,664 B

using u64t = unsigned long long;

__device__ __forceinline__ u64t pk2(float lo, float hi) {
    u64t r; asm("mov.b64 %0,{%1,%2};" : "=l"(r) : "f"(lo), "f"(hi)); return r;
}
__device__ __forceinline__ u64t dup2(float v) { return pk2(v, v); }
__device__ __forceinline__ float2 up2(u64t p) {
    float2 t; asm("mov.b64 {%0,%1},%2;" : "=f"(t.x), "=f"(t.y) : "l"(p)); return t;
}
__device__ __forceinline__ u64t f2fma(u64t a, u64t b, u64t c) {
    u64t d; asm("fma.rn.f32x2 %0,%1,%2,%3;" : "=l"(d) : "l"(a), "l"(b), "l"(c)); return d;
}
__device__ __forceinline__ u64t f2mul(u64t a, u64t b) {
    u64t d; asm("mul.rn.f32x2 %0,%1,%2;" : "=l"(d) : "l"(a), "l"(b)); return d;
}
__device__ __forceinline__ float sigm(float v) {
    return 1.0f / (1.0f + __expf(-v));
}

__global__ void __launch_bounds__(NT, 2)
e3nn_fctp_kernel(const float* __restrict__ x,
                 const float* __restrict__ l0h, const float* __restrict__ l1h, const float* __restrict__ l2h,
                 const float* __restrict__ l0a, const float* __restrict__ l1a, const float* __restrict__ l2a,
                 const float* __restrict__ w000, const float* __restrict__ w110, const float* __restrict__ w220,
                 const float* __restrict__ w011, const float* __restrict__ w101, const float* __restrict__ w121,
                 const float* __restrict__ w211, const float* __restrict__ w022, const float* __restrict__ w202,
                 const float* __restrict__ w112, const float* __restrict__ w222,
                 float* __restrict__ out, int rows)
{
    extern __shared__ float sm[];
    const int tid = threadIdx.x;

    const float s0   = 0.051031036307982884f;   // sqrt(1/384)
    const float s1   = 0.088388347648318447f;   // sqrt(3/384)
    const float i3   = 0.57735026918962576f;    // 1/sqrt(3)
    const float i6   = 0.40824829046386302f;    // 1/sqrt(6)
    const float c110 = s0 * i3;
    const float c1_3 = s1 * i3;
    const float c1_6 = s1 * i6;
    const float lin16 = 0.25f;
    const float lin8  = 0.35355339059327379f;

    // ---- preprocess TP weights into shared memory (scaled) ----
    for (int i = tid; i < 4096; i += NT)
        sm[O_W000 + i] = w000[i] * s0;
    for (int i = tid; i < 1024; i += NT) {
        sm[O_W110 + i] = w110[i] * c110;
        sm[O_W220 + i] = w220[i] * c110;
        sm[O_W011 + i] = w011[i] * c1_3;
        sm[O_W101 + i] = w101[i] * c1_3;
        sm[O_W022 + i] = w022[i] * c1_3;
        sm[O_W202 + i] = w202[i] * c1_3;
    }
    for (int i = tid; i < 512; i += NT) {
        sm[O_W121 + i] = w121[i] * c1_6;
        sm[O_W211 + i] = w211[i] * c1_6;
        sm[O_W112 + i] = w112[i] * c1_6;
        sm[O_W222 + i] = w222[i] * c1_6;
    }
    __syncthreads();

    const float* sT = sm + tid;   // lane-indexed staging base
    const int stride = gridDim.x * NT;
    #pragma unroll 1
    for (int row = blockIdx.x * NT + tid; row < rows; row += stride) {
        const float* xr = x + (size_t)row * 64u;

        // ---- irrep-1 #1 (weights via LDG.64 v-pairs): h1 -> smem, a1(normact) -> smem
        {
            float xva[24];
            #pragma unroll
            for (int q = 0; q < 6; q++) {
                float4 t = __ldg((const float4*)(xr + 16) + q);
                xva[4*q+0]=t.x*lin8; xva[4*q+1]=t.y*lin8; xva[4*q+2]=t.z*lin8; xva[4*q+3]=t.w*lin8;
            }
            u64t hp[12], ap[12];    // [v2*3+i], packed over (2v2, 2v2+1)
            #pragma unroll
            for (int j = 0; j < 12; j++) { hp[j]=0ull; ap[j]=0ull; }
            #pragma unroll
            for (int u = 0; u < 8; u++) {
                const u64t x0 = dup2(xva[u*3+0]), x1 = dup2(xva[u*3+1]), x2 = dup2(xva[u*3+2]);
                #pragma unroll
                for (int v2 = 0; v2 < 4; v2++) {
                    const u64t wh = __ldg((const u64t*)(l1h + u*8 + 2*v2));
                    const u64t wa = __ldg((const u64t*)(l1a + u*8 + 2*v2));
                    hp[v2*3+0] = f2fma(x0, wh, hp[v2*3+0]);
                    hp[v2*3+1] = f2fma(x1, wh, hp[v2*3+1]);
                    hp[v2*3+2] = f2fma(x2, wh, hp[v2*3+2]);
                    ap[v2*3+0] = f2fma(x0, wa, ap[v2*3+0]);
                    ap[v2*3+1] = f2fma(x1, wa, ap[v2*3+1]);
                    ap[v2*3+2] = f2fma(x2, wa, ap[v2*3+2]);
                }
            }
            #pragma unroll
            for (int v2 = 0; v2 < 4; v2++) {
                float2 h_0 = up2(hp[v2*3+0]), h_1 = up2(hp[v2*3+1]), h_2 = up2(hp[v2*3+2]);
                float2 a_0 = up2(ap[v2*3+0]), a_1 = up2(ap[v2*3+1]), a_2 = up2(ap[v2*3+2]);
                {
                    const int v = 2*v2;
                    sm[O_H1+(v*3+0)*NT+tid] = h_0.x;
                    sm[O_H1+(v*3+1)*NT+tid] = h_1.x;
                    sm[O_H1+(v*3+2)*NT+tid] = h_2.x;
                    const float nrm = sqrtf(a_0.x*a_0.x + a_1.x*a_1.x + a_2.x*a_2.x);
                    const float f = sigm(nrm) / ((nrm == 0.f) ? 1.f : nrm);
                    sm[O_A1+(v*3+0)*NT+tid] = a_0.x*f;
                    sm[O_A1+(v*3+1)*NT+tid] = a_1.x*f;
                    sm[O_A1+(v*3+2)*NT+tid] = a_2.x*f;
                }
                {
                    const int v = 2*v2+1;
                    sm[O_H1+(v*3+0)*NT+tid] = h_0.y;
                    sm[O_H1+(v*3+1)*NT+tid] = h_1.y;
                    sm[O_H1+(v*3+2)*NT+tid] = h_2.y;
                    const float nrm = sqrtf(a_0.y*a_0.y + a_1.y*a_1.y + a_2.y*a_2.y);
                    const float f = sigm(nrm) / ((nrm == 0.f) ? 1.f : nrm);
                    sm[O_A1+(v*3+0)*NT+tid] = a_0.y*f;
                    sm[O_A1+(v*3+1)*NT+tid] = a_1.y*f;
                    sm[O_A1+(v*3+2)*NT+tid] = a_2.y*f;
                }
            }
        }

        // ---- irrep-1 #2: h2 stays in regs, a2(normact) -> smem ----
        float h2[24];
        {
            float xvb[24];
            #pragma unroll
            for (int q = 0; q < 6; q++) {
                float4 t = __ldg((const float4*)(xr + 40) + q);
                xvb[4*q+0]=t.x*lin8; xvb[4*q+1]=t.y*lin8; xvb[4*q+2]=t.z*lin8; xvb[4*q+3]=t.w*lin8;
            }
            u64t hp[12], ap[12];
            #pragma unroll
            for (int j = 0; j < 12; j++) { hp[j]=0ull; ap[j]=0ull; }
            #pragma unroll
            for (int u = 0; u < 8; u++) {
                const u64t x0 = dup2(xvb[u*3+0]), x1 = dup2(xvb[u*3+1]), x2 = dup2(xvb[u*3+2]);
                #pragma unroll
                for (int v2 = 0; v2 < 4; v2++) {
                    const u64t wh = __ldg((const u64t*)(l2h + u*8 + 2*v2));
                    const u64t wa = __ldg((const u64t*)(l2a + u*8 + 2*v2));
                    hp[v2*3+0] = f2fma(x0, wh, hp[v2*3+0]);
                    hp[v2*3+1] = f2fma(x1, wh, hp[v2*3+1]);
                    hp[v2*3+2] = f2fma(x2, wh, hp[v2*3+2]);
                    ap[v2*3+0] = f2fma(x0, wa, ap[v2*3+0]);
                    ap[v2*3+1] = f2fma(x1, wa, ap[v2*3+1]);
                    ap[v2*3+2] = f2fma(x2, wa, ap[v2*3+2]);
                }
            }
            #pragma unroll
            for (int v2 = 0; v2 < 4; v2++) {
                float2 h_0 = up2(hp[v2*3+0]), h_1 = up2(hp[v2*3+1]), h_2 = up2(hp[v2*3+2]);
                float2 a_0 = up2(ap[v2*3+0]), a_1 = up2(ap[v2*3+1]), a_2 = up2(ap[v2*3+2]);
                {
                    const int v = 2*v2;
                    h2[v*3+0]=h_0.x; h2[v*3+1]=h_1.x; h2[v*3+2]=h_2.x;
                    const float nrm = sqrtf(a_0.x*a_0.x + a_1.x*a_1.x + a_2.x*a_2.x);
                    const float f = sigm(nrm) / ((nrm == 0.f) ? 1.f : nrm);
                    sm[O_A2+(v*3+0)*NT+tid] = a_0.x*f;
                    sm[O_A2+(v*3+1)*NT+tid] = a_1.x*f;
                    sm[O_A2+(v*3+2)*NT+tid] = a_2.x*f;
                }
                {
                    const int v = 2*v2+1;
                    h2[v*3+0]=h_0.y; h2[v*3+1]=h_1.y; h2[v*3+2]=h_2.y;
                    const float nrm = sqrtf(a_0.y*a_0.y + a_1.y*a_1.y + a_2.y*a_2.y);
                    const float f = sigm(nrm) / ((nrm == 0.f) ? 1.f : nrm);
                    sm[O_A2+(v*3+0)*NT+tid] = a_0.y*f;
                    sm[O_A2+(v*3+1)*NT+tid] = a_1.y*f;
                    sm[O_A2+(v*3+2)*NT+tid] = a_2.y*f;
                }
            }
        }

        // ---- l=0 linear (weights via LDG.128): h0 scalars, a0 scalars (post-normact)
        float h0[16], a0[16];
        {
            float xv0[16];
            #pragma unroll
            for (int q = 0; q < 4; q++) {
                float4 t = __ldg(((const float4*)xr) + q);
                xv0[4*q+0]=t.x*lin16; xv0[4*q+1]=t.y*lin16; xv0[4*q+2]=t.z*lin16; xv0[4*q+3]=t.w*lin16;
            }
            u64t h0p[8], a0p[8];
            #pragma unroll
            for (int q = 0; q < 8; q++) { h0p[q]=0ull; a0p[q]=0ull; }
            #pragma unroll
            for (int u = 0; u < 16; u++) {
                const u64t xu2 = dup2(xv0[u]);
                const ulonglong2* wh = (const ulonglong2*)(l0h + u*16);
                const ulonglong2* wa = (const ulonglong2*)(l0a + u*16);
                #pragma unroll
                for (int j = 0; j < 4; j++) {
                    const ulonglong2 th = __ldg(wh + j);
                    h0p[2*j+0] = f2fma(xu2, th.x, h0p[2*j+0]);
                    h0p[2*j+1] = f2fma(xu2, th.y, h0p[2*j+1]);
                    const ulonglong2 ta = __ldg(wa + j);
                    a0p[2*j+0] = f2fma(xu2, ta.x, a0p[2*j+0]);
                    a0p[2*j+1] = f2fma(xu2, ta.y, a0p[2*j+1]);
                }
            }
            #pragma unroll
            for (int q = 0; q < 8; q++) {
                float2 th = up2(h0p[q]); h0[2*q] = th.x; h0[2*q+1] = th.y;
                float2 ta = up2(a0p[q]);
                {
                    const float v = ta.x, nn = fabsf(v);
                    a0[2*q] = (nn == 0.f) ? 0.f : v * sigm(nn) / nn;
                }
                {
                    const float v = ta.y, nn = fabsf(v);
                    a0[2*q+1] = (nn == 0.f) ? 0.f : v * sigm(nn) / nn;
                }
            }
        }

        float* orow = out + (size_t)row * 64u;

        // ================= out0 (16 scalars, packed over w) =================
        {
            u64t o0[8];
            #pragma unroll
            for (int q = 0; q < 8; q++) o0[q] = 0ull;

            // path (0,0,0): v-chunked dup of a0 (reg-lean)
            #pragma unroll
            for (int vc = 0; vc < 2; vc++) {
                u64t a0d8[8];
                #pragma unroll
                for (int vl = 0; vl < 8; vl++) a0d8[vl] = dup2(a0[vc*8+vl]);
                #pragma unroll
                for (int u = 0; u < 16; u++) {
                    const u64t hu2 = dup2(h0[u]);
                    #pragma unroll
                    for (int vl = 0; vl < 8; vl++) {
                        const u64t p2 = f2mul(hu2, a0d8[vl]);
                        const ulonglong2* wp = (const ulonglong2*)(sm + O_W000 + (u*16 + vc*8 + vl)*16);
                        const ulonglong2 ta = wp[0], tb = wp[1];
                        o0[0]=f2fma(p2,ta.x,o0[0]); o0[1]=f2fma(p2,ta.y,o0[1]);
                        o0[2]=f2fma(p2,tb.x,o0[2]); o0[3]=f2fma(p2,tb.y,o0[3]);
                        const ulonglong2 tc = wp[2], td = wp[3];
                        o0[4]=f2fma(p2,tc.x,o0[4]); o0[5]=f2fma(p2,tc.y,o0[5]);
                        o0[6]=f2fma(p2,td.x,o0[6]); o0[7]=f2fma(p2,td.y,o0[7]);
                    }
                }
            }
            // path (1,1,0): h1 streamed from smem, a1 hoisted
            {
                float a1r[24];
                #pragma unroll
                for (int f = 0; f < 24; f++) a1r[f] = sT[O_A1 + f*NT];
                #pragma unroll
                for (int u = 0; u < 8; u++) {
                    const float hx = sT[O_H1+(u*3+0)*NT], hy = sT[O_H1+(u*3+1)*NT], hz = sT[O_H1+(u*3+2)*NT];
                    #pragma unroll
                    for (int v = 0; v < 8; v++) {
                        const float d = hx*a1r[v*3] + hy*a1r[v*3+1] + hz*a1r[v*3+2];
                        const u64t d2 = dup2(d);
                        const ulonglong2* wp = (const ulonglong2*)(sm + O_W110 + (u*8 + v)*16);
                        const ulonglong2 ta = wp[0], tb = wp[1];
                        o0[0]=f2fma(d2,ta.x,o0[0]); o0[1]=f2fma(d2,ta.y,o0[1]);
                        o0[2]=f2fma(d2,tb.x,o0[2]); o0[3]=f2fma(d2,tb.y,o0[3]);
                        const ulonglong2 tc = wp[2], td = wp[3];
                        o0[4]=f2fma(d2,tc.x,o0[4]); o0[5]=f2fma(d2,tc.y,o0[5]);
                        o0[6]=f2fma(d2,td.x,o0[6]); o0[7]=f2fma(d2,td.y,o0[7]);
                    }
                }
            }
            // path (2,2,0): h2 in regs, a2 hoisted
            {
                float a2r[24];
                #pragma unroll
                for (int f = 0; f < 24; f++) a2r[f] = sT[O_A2 + f*NT];
                #pragma unroll
                for (int u = 0; u < 8; u++) {
                    const float hx = h2[u*3], hy = h2[u*3+1], hz = h2[u*3+2];
                    #pragma unroll
                    for (int v = 0; v < 8; v++) {
                        const float d = hx*a2r[v*3] + hy*a2r[v*3+1] + hz*a2r[v*3+2];
                        const u64t d2 = dup2(d);
                        const ulonglong2* wp = (const ulonglong2*)(sm + O_W220 + (u*8 + v)*16);
                        const ulonglong2 ta = wp[0], tb = wp[1];
                        o0[0]=f2fma(d2,ta.x,o0[0]); o0[1]=f2fma(d2,ta.y,o0[1]);
                        o0[2]=f2fma(d2,tb.x,o0[2]); o0[3]=f2fma(d2,tb.y,o0[3]);
                        const ulonglong2 tc = wp[2], td = wp[3];
                        o0[4]=f2fma(d2,tc.x,o0[4]); o0[5]=f2fma(d2,tc.y,o0[5]);
                        o0[6]=f2fma(d2,td.x,o0[6]); o0[7]=f2fma(d2,td.y,o0[7]);
                    }
                }
            }
            ulonglong2* o4 = (ulonglong2*)orow;
            #pragma unroll
            for (int j = 0; j < 4; j++) {
                ulonglong2 t; t.x = o0[2*j]; t.y = o0[2*j+1];
                o4[j] = t;
            }
        }

        // ================= out1 (8x1o -> 24) =================
        {
            u64t o1[12];
            #pragma unroll
            for (int j = 0; j < 12; j++) o1[j] = 0ull;

            // path (0,1,1): M[v,w] = sum_u h0[u]*W011[u,v,w], chunked over v
            #pragma unroll
            for (int vc = 0; vc < 2; vc++) {
                u64t Mc[16];
                #pragma unroll
                for (int j = 0; j < 16; j++) Mc[j] = 0ull;
                #pragma unroll
                for (int u = 0; u < 16; u++) {
                    const u64t hu2 = dup2(h0[u]);
                    const ulonglong2* wp = (const ulonglong2*)(sm + O_W011 + u*64 + vc*32);
                    #pragma unroll
                    for (int j = 0; j < 8; j++) {
                        const ulonglong2 t = wp[j];
                        Mc[2*j+0] = f2fma(hu2, t.x, Mc[2*j+0]);
                        Mc[2*j+1] = f2fma(hu2, t.y, Mc[2*j+1]);
                    }
                }
                #pragma unroll
                for (int vl = 0; vl < 4; vl++) {
                    const int v = vc*4 + vl;
                    const u64t b0 = dup2(sT[O_A1+(v*3+0)*NT]);
                    const u64t b1 = dup2(sT[O_A1+(v*3+1)*NT]);
                    const u64t b2 = dup2(sT[O_A1+(v*3+2)*NT]);
                    #pragma unroll
                    for (int w2 = 0; w2 < 4; w2++) {
                        const u64t m = Mc[vl*4 + w2];
                        o1[w2*3+0] = f2fma(b0, m, o1[w2*3+0]);
                        o1[w2*3+1] = f2fma(b1, m, o1[w2*3+1]);
                        o1[w2*3+2] = f2fma(b2, m, o1[w2*3+2]);
                    }
                }
            }
            // path (1,0,1): M[u,w] = sum_v a0[v]*W101[u,v,w], chunked over u
            #pragma unroll
            for (int uc = 0; uc < 2; uc++) {
                u64t Mc[16];
                #pragma unroll
                for (int j = 0; j < 16; j++) Mc[j] = 0ull;
                #pragma unroll
                for (int v = 0; v < 16; v++) {
                    const u64t av2 = dup2(a0[v]);
                    #pragma unroll
                    for (int ul = 0; ul < 4; ul++) {
                        const int u = uc*4 + ul;
                        const ulonglong2* wp = (const ulonglong2*)(sm + O_W101 + u*128 + v*8);
                        const ulonglong2 ta = wp[0], tb = wp[1];
                        Mc[ul*4+0] = f2fma(av2, ta.x, Mc[ul*4+0]);
                        Mc[ul*4+1] = f2fma(av2, ta.y, Mc[ul*4+1]);
                        Mc[ul*4+2] = f2fma(av2, tb.x, Mc[ul*4+2]);
                        Mc[ul*4+3] = f2fma(av2, tb.y, Mc[ul*4+3]);
                    }
                }
                #pragma unroll
                for (int ul = 0; ul < 4; ul++) {
                    const int u = uc*4 + ul;
                    const u64t b0 = dup2(sT[O_H1+(u*3+0)*NT]);
                    const u64t b1 = dup2(sT[O_H1+(u*3+1)*NT]);
                    const u64t b2 = dup2(sT[O_H1+(u*3+2)*NT]);
                    #pragma unroll
                    for (int w2 = 0; w2 < 4; w2++) {
                        const u64t m = Mc[ul*4 + w2];
                        o1[w2*3+0] = f2fma(b0, m, o1[w2*3+0]);
                        o1[w2*3+1] = f2fma(b1, m, o1[w2*3+1]);
                        o1[w2*3+2] = f2fma(b2, m, o1[w2*3+2]);
                    }
                }
            }
            // path (1,2,1): cross(h1[u] smem, a2[v] hoisted)
            {
                float a2r[24];
                #pragma unroll
                for (int f = 0; f < 24; f++) a2r[f] = sT[O_A2 + f*NT];
                #pragma unroll
                for (int u = 0; u < 8; u++) {
                    const float ax = sT[O_H1+(u*3+0)*NT], ay = sT[O_H1+(u*3+1)*NT], az = sT[O_H1+(u*3+2)*NT];
                    #pragma unroll
                    for (int v = 0; v < 8; v++) {
                        const float bx=a2r[v*3], by=a2r[v*3+1], bz=a2r[v*3+2];
                        const u64t cx = dup2(ay*bz - az*by);
                        const u64t cy = dup2(az*bx - ax*bz);
                        const u64t cz = dup2(ax*by - ay*bx);
                        const ulonglong2* wp = (const ulonglong2*)(sm + O_W121 + (u*8+v)*8);
                        const ulonglong2 ta = wp[0], tb = wp[1];
                        const u64t wv[4] = {ta.x, ta.y, tb.x, tb.y};
                        #pragma unroll
                        for (int w2 = 0; w2 < 4; w2++) {
                            o1[w2*3+0] = f2fma(cx, wv[w2], o1[w2*3+0]);
                            o1[w2*3+1] = f2fma(cy, wv[w2], o1[w2*3+1]);
                            o1[w2*3+2] = f2fma(cz, wv[w2], o1[w2*3+2]);
                        }
                    }
                }
            }
            // path (2,1,1): cross(h2[u] regs, a1[v] hoisted)
            {
                float a1r[24];
                #pragma unroll
                for (int f = 0; f < 24; f++) a1r[f] = sT[O_A1 + f*NT];
                #pragma unroll
                for (int u = 0; u < 8; u++) {
                    const float ax = h2[u*3], ay = h2[u*3+1], az = h2[u*3+2];
                    #pragma unroll
                    for (int v = 0; v < 8; v++) {
                        const float bx=a1r[v*3], by=a1r[v*3+1], bz=a1r[v*3+2];
                        const u64t cx = dup2(ay*bz - az*by);
                        const u64t cy = dup2(az*bx - ax*bz);
                        const u64t cz = dup2(ax*by - ay*bx);
                        const ulonglong2* wp = (const ulonglong2*)(sm + O_W211 + (u*8+v)*8);
                        const ulonglong2 ta = wp[0], tb = wp[1];
                        const u64t wv[4] = {ta.x, ta.y, tb.x, tb.y};
                        #pragma unroll
                        for (int w2 = 0; w2 < 4; w2++) {
                            o1[w2*3+0] = f2fma(cx, wv[w2], o1[w2*3+0]);
                            o1[w2*3+1] = f2fma(cy, wv[w2], o1[w2*3+1]);
                            o1[w2*3+2] = f2fma(cz, wv[w2], o1[w2*3+2]);
                        }
                    }
                }
            }
            float o1s[24];
            #pragma unroll
            for (int w2 = 0; w2 < 4; w2++) {
                #pragma unroll
                for (int i = 0; i < 3; i++) {
                    float2 t = up2(o1[w2*3+i]);
                    o1s[(2*w2+0)*3+i] = t.x;
                    o1s[(2*w2+1)*3+i] = t.y;
                }
            }
            float4* o4 = (float4*)(orow + 16);
            #pragma unroll
            for (int q = 0; q < 6; q++)
                o4[q] = make_float4(o1s[4*q], o1s[4*q+1], o1s[4*q+2], o1s[4*q+3]);
        }

        // ================= out2 (8x1e -> 24) =================
        {
            u64t o2[12];
            #pragma unroll
            for (int j = 0; j < 12; j++) o2[j] = 0ull;

            // path (0,2,2): chunked over v
            #pragma unroll
            for (int vc = 0; vc < 2; vc++) {
                u64t Mc[16];
                #pragma unroll
                for (int j = 0; j < 16; j++) Mc[j] = 0ull;
                #pragma unroll
                for (int u = 0; u < 16; u++) {
                    const u64t hu2 = dup2(h0[u]);
                    const ulonglong2* wp = (const ulonglong2*)(sm + O_W022 + u*64 + vc*32);
                    #pragma unroll
                    for (int j = 0; j < 8; j++) {
                        const ulonglong2 t = wp[j];
                        Mc[2*j+0] = f2fma(hu2, t.x, Mc[2*j+0]);
                        Mc[2*j+1] = f2fma(hu2, t.y, Mc[2*j+1]);
                    }
                }
                #pragma unroll
                for (int vl = 0; vl < 4; vl++) {
                    const int v = vc*4 + vl;
                    const u64t b0 = dup2(sT[O_A2+(v*3+0)*NT]);
                    const u64t b1 = dup2(sT[O_A2+(v*3+1)*NT]);
                    const u64t b2 = dup2(sT[O_A2+(v*3+2)*NT]);
                    #pragma unroll
                    for (int w2 = 0; w2 < 4; w2++) {
                        const u64t m = Mc[vl*4 + w2];
                        o2[w2*3+0] = f2fma(b0, m, o2[w2*3+0]);
                        o2[w2*3+1] = f2fma(b1, m, o2[w2*3+1]);
                        o2[w2*3+2] = f2fma(b2, m, o2[w2*3+2]);
                    }
                }
            }
            // path (2,0,2): chunked over u, h2 regs
            #pragma unroll
            for (int uc = 0; uc < 2; uc++) {
                u64t Mc[16];
                #pragma unroll
                for (int j = 0; j < 16; j++) Mc[j] = 0ull;
                #pragma unroll
                for (int v = 0; v < 16; v++) {
                    const u64t av2 = dup2(a0[v]);
                    #pragma unroll
                    for (int ul = 0; ul < 4; ul++) {
                        const int u = uc*4 + ul;
                        const ulonglong2* wp = (const ulonglong2*)(sm + O_W202 + u*128 + v*8);
                        const ulonglong2 ta = wp[0], tb = wp[1];
                        Mc[ul*4+0] = f2fma(av2, ta.x, Mc[ul*4+0]);
                        Mc[ul*4+1] = f2fma(av2, ta.y, Mc[ul*4+1]);
                        Mc[ul*4+2] = f2fma(av2, tb.x, Mc[ul*4+2]);
                        Mc[ul*4+3] = f2fma(av2, tb.y, Mc[ul*4+3]);
                    }
                }
                #pragma unroll
                for (int ul = 0; ul < 4; ul++) {
                    const int u = uc*4 + ul;
                    const u64t b0 = dup2(h2[u*3+0]);
                    const u64t b1 = dup2(h2[u*3+1]);
                    const u64t b2 = dup2(h2[u*3+2]);
                    #pragma unroll
                    for (int w2 = 0; w2 < 4; w2++) {
                        const u64t m = Mc[ul*4 + w2];
                        o2[w2*3+0] = f2fma(b0, m, o2[w2*3+0]);
                        o2[w2*3+1] = f2fma(b1, m, o2[w2*3+1]);
                        o2[w2*3+2] = f2fma(b2, m, o2[w2*3+2]);
                    }
                }
            }
            // path (1,1,2): cross(h1[u] smem, a1[v] hoisted)
            {
                float a1r[24];
                #pragma unroll
                for (int f = 0; f < 24; f++) a1r[f] = sT[O_A1 + f*NT];
                #pragma unroll
                for (int u = 0; u < 8; u++) {
                    const float ax = sT[O_H1+(u*3+0)*NT], ay = sT[O_H1+(u*3+1)*NT], az = sT[O_H1+(u*3+2)*NT];
                    #pragma unroll
                    for (int v = 0; v < 8; v++) {
                        const float bx=a1r[v*3], by=a1r[v*3+1], bz=a1r[v*3+2];
                        const u64t cx = dup2(ay*bz - az*by);
                        const u64t cy = dup2(az*bx - ax*bz);
                        const u64t cz = dup2(ax*by - ay*bx);
                        const ulonglong2* wp = (const ulonglong2*)(sm + O_W112 + (u*8+v)*8);
                        const ulonglong2 ta = wp[0], tb = wp[1];
                        const u64t wv[4] = {ta.x, ta.y, tb.x, tb.y};
                        #pragma unroll
                        for (int w2 = 0; w2 < 4; w2++) {
                            o2[w2*3+0] = f2fma(cx, wv[w2], o2[w2*3+0]);
                            o2[w2*3+1] = f2fma(cy, wv[w2], o2[w2*3+1]);
                            o2[w2*3+2] = f2fma(cz, wv[w2], o2[w2*3+2]);
                        }
                    }
                }
            }
            // path (2,2,2): cross(h2[u] regs, a2[v] hoisted)
            {
                float a2r[24];
                #pragma unroll
                for (int f = 0; f < 24; f++) a2r[f] = sT[O_A2 + f*NT];
                #pragma unroll
                for (int u = 0; u < 8; u++) {
                    const float ax = h2[u*3], ay = h2[u*3+1], az = h2[u*3+2];
                    #pragma unroll
                    for (int v = 0; v < 8; v++) {
                        const float bx=a2r[v*3], by=a2r[v*3+1], bz=a2r[v*3+2];
                        const u64t cx = dup2(ay*bz - az*by);
                        const u64t cy = dup2(az*bx - ax*bz);
                        const u64t cz = dup2(ax*by - ay*bx);
                        const ulonglong2* wp = (const ulonglong2*)(sm + O_W222 + (u*8+v)*8);
                        const ulonglong2 ta = wp[0], tb = wp[1];
                        const u64t wv[4] = {ta.x, ta.y, tb.x, tb.y};
                        #pragma unroll
                        for (int w2 = 0; w2 < 4; w2++) {
                            o2[w2*3+0] = f2fma(cx, wv[w2], o2[w2*3+0]);
                            o2[w2*3+1] = f2fma(cy, wv[w2], o2[w2*3+1]);
                            o2[w2*3+2] = f2fma(cz, wv[w2], o2[w2*3+2]);
                        }
                    }
                }
            }
            float o2s[24];
            #pragma unroll
            for (int w2 = 0; w2 < 4; w2++) {
                #pragma unroll
                for (int i = 0; i < 3; i++) {
                    float2 t = up2(o2[w2*3+i]);
                    o2s[(2*w2+0)*3+i] = t.x;
                    o2s[(2*w2+1)*3+i] = t.y;
                }
            }
            float4* o4 = (float4*)(orow + 40);
            #pragma unroll
            for (int q = 0; q < 6; q++)
                o4[q] = make_float4(o2s[4*q], o2s[4*q+1], o2s[4*q+2], o2s[4*q+3]);
        }
    }
}

extern "C" void kernel_launch(void* const* d_in, const int* in_sizes, int n_in,
                              void* d_out, int out_size)
{
    const float* x    = (const float*)d_in[0];
    const float* l0h  = (const float*)d_in[1];
    const float* l1h  = (const float*)d_in[2];
    const float* l2h  = (const float*)d_in[3];
    const float* l0a  = (const float*)d_in[4];
    const float* l1a  = (const float*)d_in[5];
    const float* l2a  = (const float*)d_in[6];
    const float* w000 = (const float*)d_in[7];
    const float* w110 = (const float*)d_in[8];
    const float* w220 = (const float*)d_in[9];
    const float* w011 = (const float*)d_in[10];
    const float* w101 = (const float*)d_in[11];
    const float* w121 = (const float*)d_in[12];
    const float* w211 = (const float*)d_in[13];
    const float* w022 = (const float*)d_in[14];
    const float* w202 = (const float*)d_in[15];
    const float* w112 = (const float*)d_in[16];
    const float* w222 = (const float*)d_in[17];
    float* out = (float*)d_out;

    const int rows = in_sizes[0] / 64;
    const size_t smem_bytes = SMEM_FLOATS * sizeof(float);
    cudaFuncSetAttribute(e3nn_fctp_kernel,
                         cudaFuncAttributeMaxDynamicSharedMemorySize,
                         (int)smem_bytes);

    // 2 rows per thread: amortize per-CTA weight preprocessing
    const int grid = (rows + 2*NT - 1) / (2*NT);
    e3nn_fctp_kernel<<<grid, NT, smem_bytes>>>(
        x, l0h, l1h, l2h, l0a, l1a, l2a,
        w000, w110, w220, w011, w101, w121, w211, w022, w202, w112, w222,
        out, rows);
}

// round 6
// speedup vs baseline: 1.0483x; 1.0483x over previous
#include <cuda_runtime.h>
#include <cstdint>

constexpr int NT = 192;

// ---------------- shared-memory layout (floats) ----------------
constexpr int O_L0H  = 0;      // 256  (16x16)
constexpr int O_L0A  = 256;    // 256
constexpr int O_IL1  = 512;    // 128: interleaved (h,a) weights for irrep-1 linear
constexpr int O_IL2  = 640;    // 128
constexpr int O_W000 = 768;    // 4096 (16,16,16)
constexpr int O_W110 = 4864;   // 1024 (8,8,16)
constexpr int O_W220 = 5888;   // 1024
constexpr int O_W011 = 6912;   // 1024 (16,8,8)
constexpr int O_W101 = 7936;   // 1024 (8,16,8)
constexpr int O_W121 = 8960;   // 512  (8,8,8)  PAIRED over v-parity
constexpr int O_W211 = 9472;   // 512  paired
constexpr int O_W022 = 9984;   // 1024 (16,8,8)
constexpr int O_W202 = 11008;  // 1024 (8,16,8)
constexpr int O_W112 = 12032;  // 512  paired
constexpr int O_W222 = 12544;  // 512  paired
// per-thread staging: [feat][tid], lane-indexed, conflict-free
constexpr int O_H1   = 13056;             // 24*NT
constexpr int O_A1   = O_H1 + 24*NT;      // 24*NT
constexpr int O_A2   = O_A1 + 24*NT;      // 24*NT
constexpr int SMEM_FLOATS = O_A2 + 24*NT; // 13056 + 13824 = 26880 (107,520 B)

using u64t = unsigned long long;

__device__ __forceinline__ u64t pk2(float lo, float hi) {
    u64t r; asm("mov.b64 %0,{%1,%2};" : "=l"(r) : "f"(lo), "f"(hi)); return r;
}
__device__ __forceinline__ u64t dup2(float v) { return pk2(v, v); }
__device__ __forceinline__ float2 up2(u64t p) {
    float2 t; asm("mov.b64 {%0,%1},%2;" : "=f"(t.x), "=f"(t.y) : "l"(p)); return t;
}
__device__ __forceinline__ u64t f2fma(u64t a, u64t b, u64t c) {
    u64t d; asm("fma.rn.f32x2 %0,%1,%2,%3;" : "=l"(d) : "l"(a), "l"(b), "l"(c)); return d;
}
__device__ __forceinline__ u64t f2mul(u64t a, u64t b) {
    u64t d; asm("mul.rn.f32x2 %0,%1,%2;" : "=l"(d) : "l"(a), "l"(b)); return d;
}
__device__ __forceinline__ float sigm(float v) {
    return 1.0f / (1.0f + __expf(-v));
}

// Packed-over-v-parity cross path:
//   oc[w*3+c] lanes = (v even, v odd) partial sums of
//   sum_{u,v} Wp[u,v,w] * cross(h_u, b_v)[c]
// hx,hy,hz supplied per u via lambda-free macro structure below.
__device__ __forceinline__ void cross_uv2(
    const float hx, const float hy, const float hz,
    const u64t* __restrict__ bp,            // bp[v2*3+i], 12 pairs
    const float* __restrict__ wbase,        // paired weights for this u: 64 floats
    u64t* __restrict__ oc)
{
    const u64t hxd = dup2(hx), hyd = dup2(hy), hzd = dup2(hz);
    const u64t hxn = dup2(-hx), hyn = dup2(-hy), hzn = dup2(-hz);
    #pragma unroll
    for (int v2 = 0; v2 < 4; v2++) {
        const u64t bx = bp[v2*3+0], by = bp[v2*3+1], bz = bp[v2*3+2];
        const u64t cxp = f2fma(hzn, by, f2mul(hyd, bz));   // hy*bz - hz*by
        const u64t cyp = f2fma(hxn, bz, f2mul(hzd, bx));   // hz*bx - hx*bz
        const u64t czp = f2fma(hyn, bx, f2mul(hxd, by));   // hx*by - hy*bx
        const ulonglong2* wp = (const ulonglong2*)(wbase + v2*16);
        #pragma unroll
        for (int q = 0; q < 4; q++) {
            const ulonglong2 t = wp[q];
            const int w0 = 2*q, w1 = 2*q+1;
            oc[w0*3+0] = f2fma(cxp, t.x, oc[w0*3+0]);
            oc[w0*3+1] = f2fma(cyp, t.x, oc[w0*3+1]);
            oc[w0*3+2] = f2fma(czp, t.x, oc[w0*3+2]);
            oc[w1*3+0] = f2fma(cxp, t.y, oc[w1*3+0]);
            oc[w1*3+1] = f2fma(cyp, t.y, oc[w1*3+1]);
            oc[w1*3+2] = f2fma(czp, t.y, oc[w1*3+2]);
        }
    }
}

__global__ void __launch_bounds__(NT, 2)
e3nn_fctp_kernel(const float* __restrict__ x,
                 const float* __restrict__ l0h, const float* __restrict__ l1h, const float* __restrict__ l2h,
                 const float* __restrict__ l0a, const float* __restrict__ l1a, const float* __restrict__ l2a,
                 const float* __restrict__ w000, const float* __restrict__ w110, const float* __restrict__ w220,
                 const float* __restrict__ w011, const float* __restrict__ w101, const float* __restrict__ w121,
                 const float* __restrict__ w211, const float* __restrict__ w022, const float* __restrict__ w202,
                 const float* __restrict__ w112, const float* __restrict__ w222,
                 float* __restrict__ out, int rows)
{
    extern __shared__ float sm[];
    const int tid = threadIdx.x;

    const float s0   = 0.051031036307982884f;   // sqrt(1/384)
    const float s1   = 0.088388347648318447f;   // sqrt(3/384)
    const float i3   = 0.57735026918962576f;    // 1/sqrt(3)
    const float i6   = 0.40824829046386302f;    // 1/sqrt(6)
    const float c110 = s0 * i3;
    const float c1_3 = s1 * i3;
    const float c1_6 = s1 * i6;
    const float lin16 = 0.25f;
    const float lin8  = 0.35355339059327379f;

    // ---- preprocess weights into shared memory (scaled) ----
    for (int i = tid; i < 256; i += NT) {
        sm[O_L0H + i] = l0h[i] * lin16;
        sm[O_L0A + i] = l0a[i] * lin16;
    }
    for (int i = tid; i < 64; i += NT) {
        sm[O_IL1 + 2*i+0] = l1h[i] * lin8;
        sm[O_IL1 + 2*i+1] = l1a[i] * lin8;
        sm[O_IL2 + 2*i+0] = l2h[i] * lin8;
        sm[O_IL2 + 2*i+1] = l2a[i] * lin8;
    }
    for (int i = tid; i < 4096; i += NT)
        sm[O_W000 + i] = w000[i] * s0;
    for (int i = tid; i < 1024; i += NT) {
        sm[O_W110 + i] = w110[i] * c110;
        sm[O_W220 + i] = w220[i] * c110;
        sm[O_W011 + i] = w011[i] * c1_3;
        sm[O_W101 + i] = w101[i] * c1_3;
        sm[O_W022 + i] = w022[i] * c1_3;
        sm[O_W202 + i] = w202[i] * c1_3;
    }
    // cross-path weights: paired layout [u][v2][w][parity]
    for (int j = tid; j < 512; j += NT) {
        const int par = j & 1, w = (j >> 1) & 7, v2 = (j >> 4) & 3, u = j >> 6;
        const int orig = (u*8 + 2*v2 + par)*8 + w;
        sm[O_W121 + j] = w121[orig] * c1_6;
        sm[O_W211 + j] = w211[orig] * c1_6;
        sm[O_W112 + j] = w112[orig] * c1_6;
        sm[O_W222 + j] = w222[orig] * c1_6;
    }
    __syncthreads();

    const float* sT = sm + tid;   // lane-indexed staging base
    const int stride = gridDim.x * NT;
    #pragma unroll 1
    for (int row = blockIdx.x * NT + tid; row < rows; row += stride) {
        const float* xr = x + (size_t)row * 64u;

        // ---- irrep-1 #1: h1 -> smem, a1(normact) -> smem ----
        {
            float xva[24];
            #pragma unroll
            for (int q = 0; q < 6; q++) {
                float4 t = __ldg((const float4*)(xr + 16) + q);
                xva[4*q+0]=t.x; xva[4*q+1]=t.y; xva[4*q+2]=t.z; xva[4*q+3]=t.w;
            }
            u64t ha[24];
            #pragma unroll
            for (int j = 0; j < 24; j++) ha[j] = 0ull;
            #pragma unroll
            for (int u = 0; u < 8; u++) {
                const u64t x0 = dup2(xva[u*3+0]), x1 = dup2(xva[u*3+1]), x2 = dup2(xva[u*3+2]);
                #pragma unroll
                for (int v = 0; v < 8; v++) {
                    const u64t w = *(const u64t*)(sm + O_IL1 + (u*8+v)*2);
                    ha[v*3+0] = f2fma(x0, w, ha[v*3+0]);
                    ha[v*3+1] = f2fma(x1, w, ha[v*3+1]);
                    ha[v*3+2] = f2fma(x2, w, ha[v*3+2]);
                }
            }
            #pragma unroll
            for (int v = 0; v < 8; v++) {
                float2 t0 = up2(ha[v*3+0]), t1 = up2(ha[v*3+1]), t2 = up2(ha[v*3+2]);
                const float b0 = t0.y, b1 = t1.y, b2 = t2.y;
                const float nrm = sqrtf(b0*b0 + b1*b1 + b2*b2);
                const float f = sigm(nrm) / ((nrm == 0.f) ? 1.f : nrm);
                sm[O_H1 + (v*3+0)*NT + tid] = t0.x;
                sm[O_H1 + (v*3+1)*NT + tid] = t1.x;
                sm[O_H1 + (v*3+2)*NT + tid] = t2.x;
                sm[O_A1 + (v*3+0)*NT + tid] = b0*f;
                sm[O_A1 + (v*3+1)*NT + tid] = b1*f;
                sm[O_A1 + (v*3+2)*NT + tid] = b2*f;
            }
        }

        // ---- irrep-1 #2: h2 stays in regs, a2(normact) -> smem ----
        float h2[24];
        {
            float xvb[24];
            #pragma unroll
            for (int q = 0; q < 6; q++) {
                float4 t = __ldg((const float4*)(xr + 40) + q);
                xvb[4*q+0]=t.x; xvb[4*q+1]=t.y; xvb[4*q+2]=t.z; xvb[4*q+3]=t.w;
            }
            u64t ha[24];
            #pragma unroll
            for (int j = 0; j < 24; j++) ha[j] = 0ull;
            #pragma unroll
            for (int u = 0; u < 8; u++) {
                const u64t x0 = dup2(xvb[u*3+0]), x1 = dup2(xvb[u*3+1]), x2 = dup2(xvb[u*3+2]);
                #pragma unroll
                for (int v = 0; v < 8; v++) {
                    const u64t w = *(const u64t*)(sm + O_IL2 + (u*8+v)*2);
                    ha[v*3+0] = f2fma(x0, w, ha[v*3+0]);
                    ha[v*3+1] = f2fma(x1, w, ha[v*3+1]);
                    ha[v*3+2] = f2fma(x2, w, ha[v*3+2]);
                }
            }
            #pragma unroll
            for (int v = 0; v < 8; v++) {
                float2 t0 = up2(ha[v*3+0]), t1 = up2(ha[v*3+1]), t2 = up2(ha[v*3+2]);
                const float b0 = t0.y, b1 = t1.y, b2 = t2.y;
                const float nrm = sqrtf(b0*b0 + b1*b1 + b2*b2);
                const float f = sigm(nrm) / ((nrm == 0.f) ? 1.f : nrm);
                h2[v*3+0] = t0.x; h2[v*3+1] = t1.x; h2[v*3+2] = t2.x;
                sm[O_A2 + (v*3+0)*NT + tid] = b0*f;
                sm[O_A2 + (v*3+1)*NT + tid] = b1*f;
                sm[O_A2 + (v*3+2)*NT + tid] = b2*f;
            }
        }

        // ---- l=0 linear: h0 scalars, a0 scalars (post-normact) ----
        float h0[16], a0[16];
        {
            float xv0[16];
            #pragma unroll
            for (int q = 0; q < 4; q++) {
                float4 t = __ldg(((const float4*)xr) + q);
                xv0[4*q+0]=t.x; xv0[4*q+1]=t.y; xv0[4*q+2]=t.z; xv0[4*q+3]=t.w;
            }
            u64t h0p[8], a0p[8];
            #pragma unroll
            for (int q = 0; q < 8; q++) { h0p[q]=0ull; a0p[q]=0ull; }
            #pragma unroll
            for (int u = 0; u < 16; u++) {
                const u64t xu2 = dup2(xv0[u]);
                const ulonglong2* wh = (const ulonglong2*)(sm + O_L0H + u*16);
                const ulonglong2* wa = (const ulonglong2*)(sm + O_L0A + u*16);
                #pragma unroll
                for (int j = 0; j < 4; j++) {
                    const ulonglong2 th = wh[j];
                    h0p[2*j+0] = f2fma(xu2, th.x, h0p[2*j+0]);
                    h0p[2*j+1] = f2fma(xu2, th.y, h0p[2*j+1]);
                    const ulonglong2 ta = wa[j];
                    a0p[2*j+0] = f2fma(xu2, ta.x, a0p[2*j+0]);
                    a0p[2*j+1] = f2fma(xu2, ta.y, a0p[2*j+1]);
                }
            }
            #pragma unroll
            for (int q = 0; q < 8; q++) {
                float2 th = up2(h0p[q]); h0[2*q] = th.x; h0[2*q+1] = th.y;
                float2 ta = up2(a0p[q]);
                {
                    const float v = ta.x, nn = fabsf(v);
                    a0[2*q] = (nn == 0.f) ? 0.f : v * sigm(nn) / nn;
                }
                {
                    const float v = ta.y, nn = fabsf(v);
                    a0[2*q+1] = (nn == 0.f) ? 0.f : v * sigm(nn) / nn;
                }
            }
        }

        float* orow = out + (size_t)row * 64u;

        // ================= out0 (16 scalars, packed over w) =================
        {
            u64t o0[8];
            #pragma unroll
            for (int q = 0; q < 8; q++) o0[q] = 0ull;

            // path (0,0,0)
            #pragma unroll
            for (int vc = 0; vc < 2; vc++) {
                u64t a0d8[8];
                #pragma unroll
                for (int vl = 0; vl < 8; vl++) a0d8[vl] = dup2(a0[vc*8+vl]);
                #pragma unroll
                for (int u = 0; u < 16; u++) {
                    const u64t hu2 = dup2(h0[u]);
                    #pragma unroll
                    for (int vl = 0; vl < 8; vl++) {
                        const u64t p2 = f2mul(hu2, a0d8[vl]);
                        const ulonglong2* wp = (const ulonglong2*)(sm + O_W000 + (u*16 + vc*8 + vl)*16);
                        const ulonglong2 ta = wp[0], tb = wp[1];
                        o0[0]=f2fma(p2,ta.x,o0[0]); o0[1]=f2fma(p2,ta.y,o0[1]);
                        o0[2]=f2fma(p2,tb.x,o0[2]); o0[3]=f2fma(p2,tb.y,o0[3]);
                        const ulonglong2 tc = wp[2], td = wp[3];
                        o0[4]=f2fma(p2,tc.x,o0[4]); o0[5]=f2fma(p2,tc.y,o0[5]);
                        o0[6]=f2fma(p2,td.x,o0[6]); o0[7]=f2fma(p2,td.y,o0[7]);
                    }
                }
            }
            // path (1,1,0): h1 streamed from smem, a1 hoisted
            {
                float a1r[24];
                #pragma unroll
                for (int f = 0; f < 24; f++) a1r[f] = sT[O_A1 + f*NT];
                #pragma unroll
                for (int u = 0; u < 8; u++) {
                    const float hx = sT[O_H1+(u*3+0)*NT], hy = sT[O_H1+(u*3+1)*NT], hz = sT[O_H1+(u*3+2)*NT];
                    #pragma unroll
                    for (int v = 0; v < 8; v++) {
                        const float d = hx*a1r[v*3] + hy*a1r[v*3+1] + hz*a1r[v*3+2];
                        const u64t d2 = dup2(d);
                        const ulonglong2* wp = (const ulonglong2*)(sm + O_W110 + (u*8 + v)*16);
                        const ulonglong2 ta = wp[0], tb = wp[1];
                        o0[0]=f2fma(d2,ta.x,o0[0]); o0[1]=f2fma(d2,ta.y,o0[1]);
                        o0[2]=f2fma(d2,tb.x,o0[2]); o0[3]=f2fma(d2,tb.y,o0[3]);
                        const ulonglong2 tc = wp[2], td = wp[3];
                        o0[4]=f2fma(d2,tc.x,o0[4]); o0[5]=f2fma(d2,tc.y,o0[5]);
                        o0[6]=f2fma(d2,td.x,o0[6]); o0[7]=f2fma(d2,td.y,o0[7]);
                    }
                }
            }
            // path (2,2,0): h2 in regs, a2 hoisted
            {
                float a2r[24];
                #pragma unroll
                for (int f = 0; f < 24; f++) a2r[f] = sT[O_A2 + f*NT];
                #pragma unroll
                for (int u = 0; u < 8; u++) {
                    const float hx = h2[u*3], hy = h2[u*3+1], hz = h2[u*3+2];
                    #pragma unroll
                    for (int v = 0; v < 8; v++) {
                        const float d = hx*a2r[v*3] + hy*a2r[v*3+1] + hz*a2r[v*3+2];
                        const u64t d2 = dup2(d);
                        const ulonglong2* wp = (const ulonglong2*)(sm + O_W220 + (u*8 + v)*16);
                        const ulonglong2 ta = wp[0], tb = wp[1];
                        o0[0]=f2fma(d2,ta.x,o0[0]); o0[1]=f2fma(d2,ta.y,o0[1]);
                        o0[2]=f2fma(d2,tb.x,o0[2]); o0[3]=f2fma(d2,tb.y,o0[3]);
                        const ulonglong2 tc = wp[2], td = wp[3];
                        o0[4]=f2fma(d2,tc.x,o0[4]); o0[5]=f2fma(d2,tc.y,o0[5]);
                        o0[6]=f2fma(d2,td.x,o0[6]); o0[7]=f2fma(d2,td.y,o0[7]);
                    }
                }
            }
            ulonglong2* o4 = (ulonglong2*)orow;
            #pragma unroll
            for (int j = 0; j < 4; j++) {
                ulonglong2 t; t.x = o0[2*j]; t.y = o0[2*j+1];
                o4[j] = t;
            }
        }

        // ================= out1 (8x1o -> 24) =================
        {
            float o1s[24];

            // --- M paths first (w-packed accumulators) ---
            {
                u64t o1[12];
                #pragma unroll
                for (int j = 0; j < 12; j++) o1[j] = 0ull;

                // path (0,1,1): chunked over v
                #pragma unroll
                for (int vc = 0; vc < 2; vc++) {
                    u64t Mc[16];
                    #pragma unroll
                    for (int j = 0; j < 16; j++) Mc[j] = 0ull;
                    #pragma unroll
                    for (int u = 0; u < 16; u++) {
                        const u64t hu2 = dup2(h0[u]);
                        const ulonglong2* wp = (const ulonglong2*)(sm + O_W011 + u*64 + vc*32);
                        #pragma unroll
                        for (int j = 0; j < 8; j++) {
                            const ulonglong2 t = wp[j];
                            Mc[2*j+0] = f2fma(hu2, t.x, Mc[2*j+0]);
                            Mc[2*j+1] = f2fma(hu2, t.y, Mc[2*j+1]);
                        }
                    }
                    #pragma unroll
                    for (int vl = 0; vl < 4; vl++) {
                        const int v = vc*4 + vl;
                        const u64t b0 = dup2(sT[O_A1+(v*3+0)*NT]);
                        const u64t b1 = dup2(sT[O_A1+(v*3+1)*NT]);
                        const u64t b2 = dup2(sT[O_A1+(v*3+2)*NT]);
                        #pragma unroll
                        for (int w2 = 0; w2 < 4; w2++) {
                            const u64t m = Mc[vl*4 + w2];
                            o1[w2*3+0] = f2fma(b0, m, o1[w2*3+0]);
                            o1[w2*3+1] = f2fma(b1, m, o1[w2*3+1]);
                            o1[w2*3+2] = f2fma(b2, m, o1[w2*3+2]);
                        }
                    }
                }
                // path (1,0,1): chunked over u
                #pragma unroll
                for (int uc = 0; uc < 2; uc++) {
                    u64t Mc[16];
                    #pragma unroll
                    for (int j = 0; j < 16; j++) Mc[j] = 0ull;
                    #pragma unroll
                    for (int v = 0; v < 16; v++) {
                        const u64t av2 = dup2(a0[v]);
                        #pragma unroll
                        for (int ul = 0; ul < 4; ul++) {
                            const int u = uc*4 + ul;
                            const ulonglong2* wp = (const ulonglong2*)(sm + O_W101 + u*128 + v*8);
                            const ulonglong2 ta = wp[0], tb = wp[1];
                            Mc[ul*4+0] = f2fma(av2, ta.x, Mc[ul*4+0]);
                            Mc[ul*4+1] = f2fma(av2, ta.y, Mc[ul*4+1]);
                            Mc[ul*4+2] = f2fma(av2, tb.x, Mc[ul*4+2]);
                            Mc[ul*4+3] = f2fma(av2, tb.y, Mc[ul*4+3]);
                        }
                    }
                    #pragma unroll
                    for (int ul = 0; ul < 4; ul++) {
                        const int u = uc*4 + ul;
                        const u64t b0 = dup2(sT[O_H1+(u*3+0)*NT]);
                        const u64t b1 = dup2(sT[O_H1+(u*3+1)*NT]);
                        const u64t b2 = dup2(sT[O_H1+(u*3+2)*NT]);
                        #pragma unroll
                        for (int w2 = 0; w2 < 4; w2++) {
                            const u64t m = Mc[ul*4 + w2];
                            o1[w2*3+0] = f2fma(b0, m, o1[w2*3+0]);
                            o1[w2*3+1] = f2fma(b1, m, o1[w2*3+1]);
                            o1[w2*3+2] = f2fma(b2, m, o1[w2*3+2]);
                        }
                    }
                }
                #pragma unroll
                for (int w2 = 0; w2 < 4; w2++) {
                    #pragma unroll
                    for (int i = 0; i < 3; i++) {
                        float2 t = up2(o1[w2*3+i]);
                        o1s[(2*w2+0)*3+i] = t.x;
                        o1s[(2*w2+1)*3+i] = t.y;
                    }
                }
            }

            // --- cross paths (v-parity packed) ---
            {
                u64t oc[24];
                #pragma unroll
                for (int j = 0; j < 24; j++) oc[j] = 0ull;

                // path (1,2,1): h1 (smem) x a2 pairs
                {
                    u64t bp[12];
                    #pragma unroll
                    for (int v2 = 0; v2 < 4; v2++)
                        #pragma unroll
                        for (int i = 0; i < 3; i++)
                            bp[v2*3+i] = pk2(sT[O_A2+((2*v2)*3+i)*NT], sT[O_A2+((2*v2+1)*3+i)*NT]);
                    #pragma unroll
                    for (int u = 0; u < 8; u++) {
                        cross_uv2(sT[O_H1+(u*3+0)*NT], sT[O_H1+(u*3+1)*NT], sT[O_H1+(u*3+2)*NT],
                                  bp, sm + O_W121 + u*64, oc);
                    }
                }
                // path (2,1,1): h2 (regs) x a1 pairs
                {
                    u64t bp[12];
                    #pragma unroll
                    for (int v2 = 0; v2 < 4; v2++)
                        #pragma unroll
                        for (int i = 0; i < 3; i++)
                            bp[v2*3+i] = pk2(sT[O_A1+((2*v2)*3+i)*NT], sT[O_A1+((2*v2+1)*3+i)*NT]);
                    #pragma unroll
                    for (int u = 0; u < 8; u++) {
                        cross_uv2(h2[u*3+0], h2[u*3+1], h2[u*3+2],
                                  bp, sm + O_W211 + u*64, oc);
                    }
                }
                #pragma unroll
                for (int j = 0; j < 24; j++) {
                    float2 t = up2(oc[j]);
                    o1s[j] += t.x + t.y;
                }
            }

            float4* o4 = (float4*)(orow + 16);
            #pragma unroll
            for (int q = 0; q < 6; q++)
                o4[q] = make_float4(o1s[4*q], o1s[4*q+1], o1s[4*q+2], o1s[4*q+3]);
        }

        // ================= out2 (8x1e -> 24) =================
        {
            float o2s[24];

            // --- M paths ---
            {
                u64t o2[12];
                #pragma unroll
                for (int j = 0; j < 12; j++) o2[j] = 0ull;

                // path (0,2,2): chunked over v
                #pragma unroll
                for (int vc = 0; vc < 2; vc++) {
                    u64t Mc[16];
                    #pragma unroll
                    for (int j = 0; j < 16; j++) Mc[j] = 0ull;
                    #pragma unroll
                    for (int u = 0; u < 16; u++) {
                        const u64t hu2 = dup2(h0[u]);
                        const ulonglong2* wp = (const ulonglong2*)(sm + O_W022 + u*64 + vc*32);
                        #pragma unroll
                        for (int j = 0; j < 8; j++) {
                            const ulonglong2 t = wp[j];
                            Mc[2*j+0] = f2fma(hu2, t.x, Mc[2*j+0]);
                            Mc[2*j+1] = f2fma(hu2, t.y, Mc[2*j+1]);
                        }
                    }
                    #pragma unroll
                    for (int vl = 0; vl < 4; vl++) {
                        const int v = vc*4 + vl;
                        const u64t b0 = dup2(sT[O_A2+(v*3+0)*NT]);
                        const u64t b1 = dup2(sT[O_A2+(v*3+1)*NT]);
                        const u64t b2 = dup2(sT[O_A2+(v*3+2)*NT]);
                        #pragma unroll
                        for (int w2 = 0; w2 < 4; w2++) {
                            const u64t m = Mc[vl*4 + w2];
                            o2[w2*3+0] = f2fma(b0, m, o2[w2*3+0]);
                            o2[w2*3+1] = f2fma(b1, m, o2[w2*3+1]);
                            o2[w2*3+2] = f2fma(b2, m, o2[w2*3+2]);
                        }
                    }
                }
                // path (2,0,2): chunked over u, h2 regs
                #pragma unroll
                for (int uc = 0; uc < 2; uc++) {
                    u64t Mc[16];
                    #pragma unroll
                    for (int j = 0; j < 16; j++) Mc[j] = 0ull;
                    #pragma unroll
                    for (int v = 0; v < 16; v++) {
                        const u64t av2 = dup2(a0[v]);
                        #pragma unroll
                        for (int ul = 0; ul < 4; ul++) {
                            const int u = uc*4 + ul;
                            const ulonglong2* wp = (const ulonglong2*)(sm + O_W202 + u*128 + v*8);
                            const ulonglong2 ta = wp[0], tb = wp[1];
                            Mc[ul*4+0] = f2fma(av2, ta.x, Mc[ul*4+0]);
                            Mc[ul*4+1] = f2fma(av2, ta.y, Mc[ul*4+1]);
                            Mc[ul*4+2] = f2fma(av2, tb.x, Mc[ul*4+2]);
                            Mc[ul*4+3] = f2fma(av2, tb.y, Mc[ul*4+3]);
                        }
                    }
                    #pragma unroll
                    for (int ul = 0; ul < 4; ul++) {
                        const int u = uc*4 + ul;
                        const u64t b0 = dup2(h2[u*3+0]);
                        const u64t b1 = dup2(h2[u*3+1]);
                        const u64t b2 = dup2(h2[u*3+2]);
                        #pragma unroll
                        for (int w2 = 0; w2 < 4; w2++) {
                            const u64t m = Mc[ul*4 + w2];
                            o2[w2*3+0] = f2fma(b0, m, o2[w2*3+0]);
                            o2[w2*3+1] = f2fma(b1, m, o2[w2*3+1]);
                            o2[w2*3+2] = f2fma(b2, m, o2[w2*3+2]);
                        }
                    }
                }
                #pragma unroll
                for (int w2 = 0; w2 < 4; w2++) {
                    #pragma unroll
                    for (int i = 0; i < 3; i++) {
                        float2 t = up2(o2[w2*3+i]);
                        o2s[(2*w2+0)*3+i] = t.x;
                        o2s[(2*w2+1)*3+i] = t.y;
                    }
                }
            }

            // --- cross paths (v-parity packed) ---
            {
                u64t oc[24];
                #pragma unroll
                for (int j = 0; j < 24; j++) oc[j] = 0ull;

                // path (1,1,2): h1 (smem) x a1 pairs
                {
                    u64t bp[12];
                    #pragma unroll
                    for (int v2 = 0; v2 < 4; v2++)
                        #pragma unroll
                        for (int i = 0; i < 3; i++)
                            bp[v2*3+i] = pk2(sT[O_A1+((2*v2)*3+i)*NT], sT[O_A1+((2*v2+1)*3+i)*NT]);
                    #pragma unroll
                    for (int u = 0; u < 8; u++) {
                        cross_uv2(sT[O_H1+(u*3+0)*NT], sT[O_H1+(u*3+1)*NT], sT[O_H1+(u*3+2)*NT],
                                  bp, sm + O_W112 + u*64, oc);
                    }
                }
                // path (2,2,2): h2 (regs) x a2 pairs
                {
                    u64t bp[12];
                    #pragma unroll
                    for (int v2 = 0; v2 < 4; v2++)
                        #pragma unroll
                        for (int i = 0; i < 3; i++)
                            bp[v2*3+i] = pk2(sT[O_A2+((2*v2)*3+i)*NT], sT[O_A2+((2*v2+1)*3+i)*NT]);
                    #pragma unroll
                    for (int u = 0; u < 8; u++) {
                        cross_uv2(h2[u*3+0], h2[u*3+1], h2[u*3+2],
                                  bp, sm + O_W222 + u*64, oc);
                    }
                }
                #pragma unroll
                for (int j = 0; j < 24; j++) {
                    float2 t = up2(oc[j]);
                    o2s[j] += t.x + t.y;
                }
            }

            float4* o4 = (float4*)(orow + 40);
            #pragma unroll
            for (int q = 0; q < 6; q++)
                o4[q] = make_float4(o2s[4*q], o2s[4*q+1], o2s[4*q+2], o2s[4*q+3]);
        }
    }
}

extern "C" void kernel_launch(void* const* d_in, const int* in_sizes, int n_in,
                              void* d_out, int out_size)
{
    const float* x    = (const float*)d_in[0];
    const float* l0h  = (const float*)d_in[1];
    const float* l1h  = (const float*)d_in[2];
    const float* l2h  = (const float*)d_in[3];
    const float* l0a  = (const float*)d_in[4];
    const float* l1a  = (const float*)d_in[5];
    const float* l2a  = (const float*)d_in[6];
    const float* w000 = (const float*)d_in[7];
    const float* w110 = (const float*)d_in[8];
    const float* w220 = (const float*)d_in[9];
    const float* w011 = (const float*)d_in[10];
    const float* w101 = (const float*)d_in[11];
    const float* w121 = (const float*)d_in[12];
    const float* w211 = (const float*)d_in[13];
    const float* w022 = (const float*)d_in[14];
    const float* w202 = (const float*)d_in[15];
    const float* w112 = (const float*)d_in[16];
    const float* w222 = (const float*)d_in[17];
    float* out = (float*)d_out;

    const int rows = in_sizes[0] / 64;
    const size_t smem_bytes = SMEM_FLOATS * sizeof(float);
    cudaFuncSetAttribute(e3nn_fctp_kernel,
                         cudaFuncAttributeMaxDynamicSharedMemorySize,
                         (int)smem_bytes);

    const int grid = (rows + 2*NT - 1) / (2*NT);
    e3nn_fctp_kernel<<<grid, NT, smem_bytes>>>(
        x, l0h, l1h, l2h, l0a, l1a, l2a,
        w000, w110, w220, w011, w101, w121, w211, w022, w202, w112, w222,
        out, rows);
}